// round 3
// baseline (speedup 1.0000x reference)
#include <cuda_runtime.h>

#define NODES 8192
#define IN_DIM 512
#define HID 128
#define OUT_DIM 64

// Scratch (device globals — no allocation allowed)
__device__ float g_Y0[NODES * HID];
__device__ float g_Y1[NODES * HID];
__device__ float g_Y2[NODES * HID];
__device__ float g_X1[NODES * HID];
__device__ float g_X2[NODES * HID];

// ---------------------------------------------------------------------------
// Classic register-tiled SGEMM: C[M,N] = A[M,K] @ B[K,N], all row-major fp32.
// BM=BN=64, BK=16, per-thread 4x4 microtile, 256 threads.
// Shapes guaranteed: M % BM == 0, N % BN == 0, K % BK == 0 for this problem.
// ---------------------------------------------------------------------------
template <int BM, int BN, int BK, int TM, int TN>
__global__ void __launch_bounds__(256, 2)
sgemm_kernel(int M, int N, int K,
             const float* __restrict__ A,
             const float* __restrict__ B,
             float* __restrict__ C) {
    __shared__ float As[BK][BM];   // transposed A tile for coalesced compute reads
    __shared__ float Bs[BK][BN];

    constexpr int NUM_THREADS = (BM / TM) * (BN / TN);
    const int tid = threadIdx.x;
    const int block_row = blockIdx.y * BM;
    const int block_col = blockIdx.x * BN;

    constexpr int TCOLS = BN / TN;
    const int trow = (tid / TCOLS) * TM;
    const int tcol = (tid % TCOLS) * TN;

    float acc[TM][TN];
#pragma unroll
    for (int i = 0; i < TM; i++)
#pragma unroll
        for (int j = 0; j < TN; j++) acc[i][j] = 0.0f;

    float ar[TM], br[TN];

    for (int k0 = 0; k0 < K; k0 += BK) {
        // ---- load A tile (BM x BK) as float4 along K, store transposed ----
#pragma unroll
        for (int i = tid; i < (BM * BK) / 4; i += NUM_THREADS) {
            const int r  = i / (BK / 4);
            const int c4 = i % (BK / 4);
            float4 v = *reinterpret_cast<const float4*>(
                &A[(size_t)(block_row + r) * K + k0 + c4 * 4]);
            As[c4 * 4 + 0][r] = v.x;
            As[c4 * 4 + 1][r] = v.y;
            As[c4 * 4 + 2][r] = v.z;
            As[c4 * 4 + 3][r] = v.w;
        }
        // ---- load B tile (BK x BN) as float4 ----
#pragma unroll
        for (int i = tid; i < (BK * BN) / 4; i += NUM_THREADS) {
            const int r  = i / (BN / 4);
            const int c4 = i % (BN / 4);
            float4 v = *reinterpret_cast<const float4*>(
                &B[(size_t)(k0 + r) * N + block_col + c4 * 4]);
            *reinterpret_cast<float4*>(&Bs[r][c4 * 4]) = v;
        }
        __syncthreads();

#pragma unroll
        for (int kk = 0; kk < BK; kk++) {
#pragma unroll
            for (int i = 0; i < TM; i++) ar[i] = As[kk][trow + i];
#pragma unroll
            for (int j = 0; j < TN; j++) br[j] = Bs[kk][tcol + j];
#pragma unroll
            for (int i = 0; i < TM; i++)
#pragma unroll
                for (int j = 0; j < TN; j++)
                    acc[i][j] = fmaf(ar[i], br[j], acc[i][j]);
        }
        __syncthreads();
    }

    // ---- epilogue: vectorized store ----
#pragma unroll
    for (int i = 0; i < TM; i++) {
#pragma unroll
        for (int j = 0; j < TN; j += 4) {
            float4 v = make_float4(acc[i][j], acc[i][j + 1], acc[i][j + 2], acc[i][j + 3]);
            *reinterpret_cast<float4*>(
                &C[(size_t)(block_row + trow + i) * N + block_col + tcol + j]) = v;
        }
    }
}

// ---------------------------------------------------------------------------
// Elementwise combine: out = act(h0*Y0 + h1*Y1 + h2*Y2 + b[col])
// ---------------------------------------------------------------------------
__global__ void combine_kernel(int total, int N,
                               const float* __restrict__ Y0,
                               const float* __restrict__ Y1,
                               const float* __restrict__ Y2,
                               const float* __restrict__ h,
                               const float* __restrict__ b,
                               float* __restrict__ out,
                               int do_relu) {
    const int idx = blockIdx.x * blockDim.x + threadIdx.x;
    if (idx >= total) return;
    const int j = idx % N;
    float v = fmaf(h[0], Y0[idx], fmaf(h[1], Y1[idx], fmaf(h[2], Y2[idx], b[j])));
    out[idx] = do_relu ? fmaxf(v, 0.0f) : v;
}

// ---------------------------------------------------------------------------

static inline void run_gemm(const float* A, const float* B, float* C,
                            int M, int N, int K) {
    dim3 grid(N / 64, M / 64);
    sgemm_kernel<64, 64, 16, 4, 4><<<grid, 256>>>(M, N, K, A, B, C);
}

extern "C" void kernel_launch(void* const* d_in, const int* in_sizes, int n_in,
                              void* d_out, int out_size) {
    const float* S  = (const float*)d_in[0];
    const float* X  = (const float*)d_in[1];
    const float* W1 = (const float*)d_in[2];
    const float* h1 = (const float*)d_in[3];
    const float* b1 = (const float*)d_in[4];
    const float* W2 = (const float*)d_in[5];
    const float* h2 = (const float*)d_in[6];
    const float* b2 = (const float*)d_in[7];
    const float* W3 = (const float*)d_in[8];
    const float* h3 = (const float*)d_in[9];
    const float* b3 = (const float*)d_in[10];
    float* out = (float*)d_out;

    float *Y0, *Y1, *Y2, *X1, *X2;
    cudaGetSymbolAddress((void**)&Y0, g_Y0);
    cudaGetSymbolAddress((void**)&Y1, g_Y1);
    cudaGetSymbolAddress((void**)&Y2, g_Y2);
    cudaGetSymbolAddress((void**)&X1, g_X1);
    cudaGetSymbolAddress((void**)&X2, g_X2);

    const int threads = 256;

    // ---------- layer 1: X[8192,512] -> X1[8192,128], ReLU ----------
    run_gemm(X,  W1, Y0, NODES, HID, IN_DIM);   // Y0 = X @ W1
    run_gemm(S,  Y0, Y1, NODES, HID, NODES);    // Y1 = S @ Y0
    run_gemm(S,  Y1, Y2, NODES, HID, NODES);    // Y2 = S @ Y1
    {
        int total = NODES * HID;
        combine_kernel<<<(total + threads - 1) / threads, threads>>>(
            total, HID, Y0, Y1, Y2, h1, b1, X1, 1);
    }

    // ---------- layer 2: X1[8192,128] -> X2[8192,128], ReLU ----------
    run_gemm(X1, W2, Y0, NODES, HID, HID);
    run_gemm(S,  Y0, Y1, NODES, HID, NODES);
    run_gemm(S,  Y1, Y2, NODES, HID, NODES);
    {
        int total = NODES * HID;
        combine_kernel<<<(total + threads - 1) / threads, threads>>>(
            total, HID, Y0, Y1, Y2, h2, b2, X2, 1);
    }

    // ---------- layer 3: X2[8192,128] -> out[8192,64], identity ----------
    run_gemm(X2, W3, Y0, NODES, OUT_DIM, HID);
    run_gemm(S,  Y0, Y1, NODES, OUT_DIM, NODES);
    run_gemm(S,  Y1, Y2, NODES, OUT_DIM, NODES);
    {
        int total = NODES * OUT_DIM;
        combine_kernel<<<(total + threads - 1) / threads, threads>>>(
            total, OUT_DIM, Y0, Y1, Y2, h3, b3, out, 0);
    }
}

// round 5
// speedup vs baseline: 4.2075x; 4.2075x over previous
#include <cuda_runtime.h>
#include <cuda_bf16.h>
#include <cstdint>

#define NODES 8192
#define IN_DIM 512
#define HID 128
#define OUT_DIM 64

// ---------------------------------------------------------------------------
// Scratch (device globals — allocation is forbidden)
// ---------------------------------------------------------------------------
__device__ __nv_bfloat16 g_Sh[(size_t)NODES * NODES];   // 128 MB
__device__ __nv_bfloat16 g_Sl[(size_t)NODES * NODES];   // 128 MB
__device__ __nv_bfloat16 g_Ah[(size_t)NODES * IN_DIM];
__device__ __nv_bfloat16 g_Al[(size_t)NODES * IN_DIM];
__device__ __nv_bfloat16 g_Bh[(size_t)HID * NODES];
__device__ __nv_bfloat16 g_Bl[(size_t)HID * NODES];
__device__ float g_Y0[NODES * HID];
__device__ float g_Y1[NODES * HID];
__device__ float g_Y2[NODES * HID];
__device__ float g_X1[NODES * HID];
__device__ float g_X2[NODES * HID];

// ---------------------------------------------------------------------------
// PTX helpers (base sm_103-safe only: cp.async, ldmatrix, mma.sync)
// ---------------------------------------------------------------------------
__device__ __forceinline__ uint32_t smem_u32(const void* p) {
    uint32_t a;
    asm("{ .reg .u64 t; cvta.to.shared.u64 t, %1; cvt.u32.u64 %0, t; }"
        : "=r"(a) : "l"(p));
    return a;
}

#define SW128(off) ((off) ^ (((off) >> 3) & 0x70))

__device__ __forceinline__ void cp16(uint32_t saddr, const void* g) {
    asm volatile("cp.async.cg.shared.global [%0], [%1], 16;" :: "r"(saddr), "l"(g));
}
#define CP_COMMIT() asm volatile("cp.async.commit_group;" ::: "memory")
#define CP_WAIT0()  asm volatile("cp.async.wait_group 0;" ::: "memory")
#define CP_WAIT1()  asm volatile("cp.async.wait_group 1;" ::: "memory")

#define LDSM_X4(r, addr)                                                        \
    asm volatile("ldmatrix.sync.aligned.m8n8.x4.shared.b16 {%0,%1,%2,%3}, [%4];" \
                 : "=r"((r)[0]), "=r"((r)[1]), "=r"((r)[2]), "=r"((r)[3])        \
                 : "r"(addr))

#define MMA16816(d, a, b)                                                        \
    asm volatile(                                                                \
        "mma.sync.aligned.m16n8k16.row.col.f32.bf16.bf16.f32 "                   \
        "{%0,%1,%2,%3}, {%4,%5,%6,%7}, {%8,%9}, {%0,%1,%2,%3};"                  \
        : "+f"((d)[0]), "+f"((d)[1]), "+f"((d)[2]), "+f"((d)[3])                 \
        : "r"((a)[0]), "r"((a)[1]), "r"((a)[2]), "r"((a)[3]),                    \
          "r"((b)[0]), "r"((b)[1]))

// ---------------------------------------------------------------------------
// bf16 hi/lo split (same layout)
// ---------------------------------------------------------------------------
__global__ void split_kernel(const float4* __restrict__ in,
                             uint2* __restrict__ hi, uint2* __restrict__ lo, int n4) {
    int i = blockIdx.x * blockDim.x + threadIdx.x;
    if (i >= n4) return;
    float4 v = in[i];
    __nv_bfloat16 h0 = __float2bfloat16(v.x), h1 = __float2bfloat16(v.y);
    __nv_bfloat16 h2 = __float2bfloat16(v.z), h3 = __float2bfloat16(v.w);
    __nv_bfloat16 l0 = __float2bfloat16(v.x - __bfloat162float(h0));
    __nv_bfloat16 l1 = __float2bfloat16(v.y - __bfloat162float(h1));
    __nv_bfloat16 l2 = __float2bfloat16(v.z - __bfloat162float(h2));
    __nv_bfloat16 l3 = __float2bfloat16(v.w - __bfloat162float(h3));
    uint2 uh, ul;
    uh.x = (uint32_t)__bfloat16_as_ushort(h0) | ((uint32_t)__bfloat16_as_ushort(h1) << 16);
    uh.y = (uint32_t)__bfloat16_as_ushort(h2) | ((uint32_t)__bfloat16_as_ushort(h3) << 16);
    ul.x = (uint32_t)__bfloat16_as_ushort(l0) | ((uint32_t)__bfloat16_as_ushort(l1) << 16);
    ul.y = (uint32_t)__bfloat16_as_ushort(l2) | ((uint32_t)__bfloat16_as_ushort(l3) << 16);
    hi[i] = uh;
    lo[i] = ul;
}

// Transpose + split: in[R,C] fp32 row-major -> hi/lo[C,R] bf16 row-major
__global__ void tsplit_kernel(const float* __restrict__ in,
                              __nv_bfloat16* __restrict__ hi,
                              __nv_bfloat16* __restrict__ lo, int R, int C) {
    __shared__ float t[32][33];
    int bx = blockIdx.x * 32;  // col base
    int by = blockIdx.y * 32;  // row base
    int tx = threadIdx.x, ty = threadIdx.y;
#pragma unroll
    for (int j = 0; j < 32; j += 8)
        t[ty + j][tx] = in[(size_t)(by + ty + j) * C + bx + tx];
    __syncthreads();
#pragma unroll
    for (int j = 0; j < 32; j += 8) {
        float v = t[tx][ty + j];
        __nv_bfloat16 h = __float2bfloat16(v);
        __nv_bfloat16 l = __float2bfloat16(v - __bfloat162float(h));
        size_t o = (size_t)(bx + ty + j) * R + by + tx;
        hi[o] = h;
        lo[o] = l;
    }
}

// ---------------------------------------------------------------------------
// Split-GEMM on mma.sync (HMMA): C[M,BN] = A[M,K] @ B[BN,K]^T
//   A, B given as bf16 hi+lo pairs; D = Ah*Bh + Ah*Bl + Al*Bh (fp32 accum).
//   BM=64, BK=64, 8 warps (2 x 4), double-buffered cp.async, SW128 smem.
// ---------------------------------------------------------------------------
template <int BN>
__global__ void __launch_bounds__(256)
gemm_mma_kernel(const __nv_bfloat16* __restrict__ Ah, const __nv_bfloat16* __restrict__ Al,
                const __nv_bfloat16* __restrict__ Bh, const __nv_bfloat16* __restrict__ Bl,
                float* __restrict__ C, int K) {
    constexpr int BM = 64, BK = 64;
    constexpr uint32_t ATILE = BM * BK * 2;           // 8192 B
    constexpr uint32_t BTILE = BN * BK * 2;           // 16384 / 8192 B
    constexpr uint32_t STAGE = 2 * ATILE + 2 * BTILE; // one stage: Ah,Al,Bh,Bl

    extern __shared__ __align__(1024) char smem[];
    const uint32_t sb = smem_u32(smem);

    const int tid = threadIdx.x;
    const int lane = tid & 31, wid = tid >> 5;
    const int warp_m = wid & 1;        // 2 m-blocks of 32
    const int warp_n = wid >> 1;       // 4 n-blocks of WTN
    constexpr int WTN = BN / 4;        // 32 or 16
    constexpr int NTILES = WTN / 8;    // 4 or 2 (n8 mma tiles per warp)
    constexpr int NPAIR = NTILES / 2;  // x4-ldmatrix pairs
    const int row0 = blockIdx.x * BM;

    float acc[2][NTILES][4];
#pragma unroll
    for (int i = 0; i < 2; i++)
#pragma unroll
        for (int j = 0; j < NTILES; j++)
#pragma unroll
            for (int k = 0; k < 4; k++) acc[i][j][k] = 0.0f;

    const int nst = K >> 6;

    auto load_stage = [&](int s) {
        const uint32_t base = sb + (uint32_t)(s & 1) * STAGE;
        const int k0 = s * BK;
        // A hi+lo: 64 rows x 8 granules of 16B
#pragma unroll
        for (int i = 0; i < 2; i++) {
            int id = tid + i * 256;
            int r = id >> 3, kg = id & 7;
            uint32_t so = SW128((uint32_t)(r * 128 + kg * 16));
            size_t go = (size_t)(row0 + r) * K + k0 + kg * 8;
            cp16(base + so, Ah + go);
            cp16(base + ATILE + so, Al + go);
        }
        // B hi+lo: BN rows x 8 granules
#pragma unroll
        for (int i = 0; i < (BN * 8) / 256; i++) {
            int id = tid + i * 256;
            int r = id >> 3, kg = id & 7;
            uint32_t so = SW128((uint32_t)(r * 128 + kg * 16));
            size_t go = (size_t)r * K + k0 + kg * 8;
            cp16(base + 2 * ATILE + so, Bh + go);
            cp16(base + 2 * ATILE + BTILE + so, Bl + go);
        }
    };

    // ldmatrix lane-address components (constant per thread)
    const int a_row = warp_m * 32 + (lane & 15);
    const int a_colb = (lane >> 4) << 4;                       // 0 or 16 bytes (k0/k8)
    const int b_row = warp_n * WTN + (lane & 7) + ((lane >> 4) << 3);
    const int b_colb = ((lane >> 3) & 1) << 4;

    load_stage(0);
    CP_COMMIT();

    for (int s = 0; s < nst; s++) {
        if (s + 1 < nst) {
            load_stage(s + 1);
            CP_COMMIT();
            CP_WAIT1();
        } else {
            CP_WAIT0();
        }
        __syncthreads();

        const uint32_t base = sb + (uint32_t)(s & 1) * STAGE;
#pragma unroll
        for (int ks = 0; ks < 4; ks++) {
            uint32_t ah[2][4], al[2][4];
#pragma unroll
            for (int mt = 0; mt < 2; mt++) {
                uint32_t off =
                    SW128((uint32_t)((a_row + mt * 16) * 128 + ks * 32 + a_colb));
                LDSM_X4(ah[mt], base + off);
                LDSM_X4(al[mt], base + ATILE + off);
            }
            uint32_t bh[NTILES][2], bl[NTILES][2];
#pragma unroll
            for (int p = 0; p < NPAIR; p++) {
                uint32_t off =
                    SW128((uint32_t)((b_row + p * 16) * 128 + ks * 32 + b_colb));
                uint32_t th[4], tl[4];
                LDSM_X4(th, base + 2 * ATILE + off);
                LDSM_X4(tl, base + 2 * ATILE + BTILE + off);
                bh[2 * p][0] = th[0]; bh[2 * p][1] = th[1];
                bh[2 * p + 1][0] = th[2]; bh[2 * p + 1][1] = th[3];
                bl[2 * p][0] = tl[0]; bl[2 * p][1] = tl[1];
                bl[2 * p + 1][0] = tl[2]; bl[2 * p + 1][1] = tl[3];
            }
#pragma unroll
            for (int mt = 0; mt < 2; mt++)
#pragma unroll
                for (int nt = 0; nt < NTILES; nt++) {
                    MMA16816(acc[mt][nt], ah[mt], bh[nt]);
                    MMA16816(acc[mt][nt], ah[mt], bl[nt]);
                    MMA16816(acc[mt][nt], al[mt], bh[nt]);
                }
        }
        __syncthreads();
    }

    // epilogue
    const int m_base = row0 + warp_m * 32;
    const int n_base = warp_n * WTN;
#pragma unroll
    for (int mt = 0; mt < 2; mt++) {
#pragma unroll
        for (int nt = 0; nt < NTILES; nt++) {
            int r = m_base + mt * 16 + (lane >> 2);
            int c = n_base + nt * 8 + (lane & 3) * 2;
            *reinterpret_cast<float2*>(&C[(size_t)r * BN + c]) =
                make_float2(acc[mt][nt][0], acc[mt][nt][1]);
            *reinterpret_cast<float2*>(&C[(size_t)(r + 8) * BN + c]) =
                make_float2(acc[mt][nt][2], acc[mt][nt][3]);
        }
    }
}

// ---------------------------------------------------------------------------
// Elementwise combine: out = act(h0*Y0 + h1*Y1 + h2*Y2 + b[col]), vectorized
// ---------------------------------------------------------------------------
__global__ void combine_kernel(int total4, int N,
                               const float4* __restrict__ Y0,
                               const float4* __restrict__ Y1,
                               const float4* __restrict__ Y2,
                               const float* __restrict__ h,
                               const float* __restrict__ b,
                               float4* __restrict__ out, int do_relu) {
    int i = blockIdx.x * blockDim.x + threadIdx.x;
    if (i >= total4) return;
    int j = (i * 4) & (N - 1);
    float h0 = h[0], h1 = h[1], h2 = h[2];
    float4 a = Y0[i], c = Y1[i], d = Y2[i];
    float4 r;
    r.x = fmaf(h0, a.x, fmaf(h1, c.x, fmaf(h2, d.x, b[j])));
    r.y = fmaf(h0, a.y, fmaf(h1, c.y, fmaf(h2, d.y, b[j + 1])));
    r.z = fmaf(h0, a.z, fmaf(h1, c.z, fmaf(h2, d.z, b[j + 2])));
    r.w = fmaf(h0, a.w, fmaf(h1, c.w, fmaf(h2, d.w, b[j + 3])));
    if (do_relu) {
        r.x = fmaxf(r.x, 0.f); r.y = fmaxf(r.y, 0.f);
        r.z = fmaxf(r.z, 0.f); r.w = fmaxf(r.w, 0.f);
    }
    out[i] = r;
}

// ---------------------------------------------------------------------------
// Host orchestration
// ---------------------------------------------------------------------------
static void run_split(const float* x, __nv_bfloat16* hi, __nv_bfloat16* lo, size_t n) {
    int n4 = (int)(n / 4);
    split_kernel<<<(n4 + 255) / 256, 256>>>((const float4*)x, (uint2*)hi, (uint2*)lo, n4);
}

static void run_tsplit(const float* in, __nv_bfloat16* hi, __nv_bfloat16* lo, int R, int C) {
    dim3 grid(C / 32, R / 32), block(32, 8);
    tsplit_kernel<<<grid, block>>>(in, hi, lo, R, C);
}

template <int BN>
static void run_gemm(const __nv_bfloat16* Ah, const __nv_bfloat16* Al,
                     const __nv_bfloat16* Bh, const __nv_bfloat16* Bl,
                     float* C, int K) {
    constexpr uint32_t STAGE = 2 * (64 * 64 * 2) + 2 * (BN * 64 * 2);
    constexpr uint32_t smem_bytes = 2 * STAGE;
    static bool configured = false;  // attribute is idempotent; set every call is also fine
    cudaFuncSetAttribute(gemm_mma_kernel<BN>,
                         cudaFuncAttributeMaxDynamicSharedMemorySize, smem_bytes);
    (void)configured;
    gemm_mma_kernel<BN><<<NODES / 64, 256, smem_bytes>>>(Ah, Al, Bh, Bl, C, K);
}

static void run_combine(const float* Y0, const float* Y1, const float* Y2,
                        const float* h, const float* b, float* out, int N, int relu) {
    int total4 = NODES * N / 4;
    combine_kernel<<<(total4 + 255) / 256, 256>>>(
        total4, N, (const float4*)Y0, (const float4*)Y1, (const float4*)Y2, h, b,
        (float4*)out, relu);
}

extern "C" void kernel_launch(void* const* d_in, const int* in_sizes, int n_in,
                              void* d_out, int out_size) {
    const float* S  = (const float*)d_in[0];
    const float* X  = (const float*)d_in[1];
    const float* W1 = (const float*)d_in[2];
    const float* h1 = (const float*)d_in[3];
    const float* b1 = (const float*)d_in[4];
    const float* W2 = (const float*)d_in[5];
    const float* h2 = (const float*)d_in[6];
    const float* b2 = (const float*)d_in[7];
    const float* W3 = (const float*)d_in[8];
    const float* h3 = (const float*)d_in[9];
    const float* b3 = (const float*)d_in[10];
    float* out = (float*)d_out;

    __nv_bfloat16 *Sh, *Sl, *Ah, *Al, *Bh, *Bl;
    float *Y0, *Y1, *Y2, *X1, *X2;
    cudaGetSymbolAddress((void**)&Sh, g_Sh);
    cudaGetSymbolAddress((void**)&Sl, g_Sl);
    cudaGetSymbolAddress((void**)&Ah, g_Ah);
    cudaGetSymbolAddress((void**)&Al, g_Al);
    cudaGetSymbolAddress((void**)&Bh, g_Bh);
    cudaGetSymbolAddress((void**)&Bl, g_Bl);
    cudaGetSymbolAddress((void**)&Y0, g_Y0);
    cudaGetSymbolAddress((void**)&Y1, g_Y1);
    cudaGetSymbolAddress((void**)&Y2, g_Y2);
    cudaGetSymbolAddress((void**)&X1, g_X1);
    cudaGetSymbolAddress((void**)&X2, g_X2);

    // S -> bf16 hi/lo (recomputed every launch: determinism rules forbid caching)
    run_split(S, Sh, Sl, (size_t)NODES * NODES);

    // -------- layer 1 (N=128, ReLU) --------
    run_split(X, Ah, Al, (size_t)NODES * IN_DIM);
    run_tsplit(W1, Bh, Bl, IN_DIM, HID);          // W1^T: [128,512]
    run_gemm<HID>(Ah, Al, Bh, Bl, Y0, IN_DIM);    // Y0 = X@W1
    run_tsplit(Y0, Bh, Bl, NODES, HID);           // Y0^T: [128,8192]
    run_gemm<HID>(Sh, Sl, Bh, Bl, Y1, NODES);     // Y1 = S@Y0
    run_tsplit(Y1, Bh, Bl, NODES, HID);
    run_gemm<HID>(Sh, Sl, Bh, Bl, Y2, NODES);     // Y2 = S@Y1
    run_combine(Y0, Y1, Y2, h1, b1, X1, HID, 1);

    // -------- layer 2 (N=128, ReLU) --------
    run_split(X1, Ah, Al, (size_t)NODES * HID);
    run_tsplit(W2, Bh, Bl, HID, HID);             // [128,128]
    run_gemm<HID>(Ah, Al, Bh, Bl, Y0, HID);
    run_tsplit(Y0, Bh, Bl, NODES, HID);
    run_gemm<HID>(Sh, Sl, Bh, Bl, Y1, NODES);
    run_tsplit(Y1, Bh, Bl, NODES, HID);
    run_gemm<HID>(Sh, Sl, Bh, Bl, Y2, NODES);
    run_combine(Y0, Y1, Y2, h2, b2, X2, HID, 1);

    // -------- layer 3 (N=64, identity) --------
    run_split(X2, Ah, Al, (size_t)NODES * HID);
    run_tsplit(W3, Bh, Bl, HID, OUT_DIM);         // [64,128]
    run_gemm<OUT_DIM>(Ah, Al, Bh, Bl, Y0, HID);
    run_tsplit(Y0, Bh, Bl, NODES, OUT_DIM);       // [64,8192]
    run_gemm<OUT_DIM>(Sh, Sl, Bh, Bl, Y1, NODES);
    run_tsplit(Y1, Bh, Bl, NODES, OUT_DIM);
    run_gemm<OUT_DIM>(Sh, Sl, Bh, Bl, Y2, NODES);
    run_combine(Y0, Y1, Y2, h3, b3, out, OUT_DIM, 0);
}

// round 7
// speedup vs baseline: 4.6767x; 1.1115x over previous
#include <cuda_runtime.h>
#include <cuda_bf16.h>
#include <cstdint>

#define NODES 8192
#define IN_DIM 512
#define HID 128
#define OUT_DIM 64

// ---------------------------------------------------------------------------
// Scratch (device globals — allocation is forbidden)
// ---------------------------------------------------------------------------
__device__ __nv_bfloat16 g_Sh[(size_t)NODES * NODES];   // 128 MB
__device__ __nv_bfloat16 g_Sl[(size_t)NODES * NODES];   // 128 MB
__device__ __nv_bfloat16 g_Ah[(size_t)NODES * IN_DIM];
__device__ __nv_bfloat16 g_Al[(size_t)NODES * IN_DIM];
__device__ __nv_bfloat16 g_Bh[(size_t)HID * NODES];
__device__ __nv_bfloat16 g_Bl[(size_t)HID * NODES];
__device__ float g_Y0[NODES * HID];
__device__ float g_Y1[NODES * HID];
__device__ float g_P[2 * NODES * HID];   // split-K partials (slice0 | slice1)
__device__ float g_X1[NODES * HID];
__device__ float g_X2[NODES * HID];

// ---------------------------------------------------------------------------
// PTX helpers (base sm_103-safe only: cp.async, ldmatrix, mma.sync)
// ---------------------------------------------------------------------------
__device__ __forceinline__ uint32_t smem_u32(const void* p) {
    uint32_t a;
    asm("{ .reg .u64 t; cvta.to.shared.u64 t, %1; cvt.u32.u64 %0, t; }"
        : "=r"(a) : "l"(p));
    return a;
}

#define SW128(off) ((off) ^ (((off) >> 3) & 0x70))

__device__ __forceinline__ void cp16(uint32_t saddr, const void* g) {
    asm volatile("cp.async.cg.shared.global [%0], [%1], 16;" :: "r"(saddr), "l"(g));
}
#define CP_COMMIT() asm volatile("cp.async.commit_group;" ::: "memory")
#define CP_WAIT0()  asm volatile("cp.async.wait_group 0;" ::: "memory")
#define CP_WAIT1()  asm volatile("cp.async.wait_group 1;" ::: "memory")

#define LDSM_X4(r, addr)                                                        \
    asm volatile("ldmatrix.sync.aligned.m8n8.x4.shared.b16 {%0,%1,%2,%3}, [%4];" \
                 : "=r"((r)[0]), "=r"((r)[1]), "=r"((r)[2]), "=r"((r)[3])        \
                 : "r"(addr))

#define MMA16816(d, a, b)                                                        \
    asm volatile(                                                                \
        "mma.sync.aligned.m16n8k16.row.col.f32.bf16.bf16.f32 "                   \
        "{%0,%1,%2,%3}, {%4,%5,%6,%7}, {%8,%9}, {%0,%1,%2,%3};"                  \
        : "+f"((d)[0]), "+f"((d)[1]), "+f"((d)[2]), "+f"((d)[3])                 \
        : "r"((a)[0]), "r"((a)[1]), "r"((a)[2]), "r"((a)[3]),                    \
          "r"((b)[0]), "r"((b)[1]))

// ---------------------------------------------------------------------------
// bf16 hi/lo split (same layout)
// ---------------------------------------------------------------------------
__global__ void split_kernel(const float4* __restrict__ in,
                             uint2* __restrict__ hi, uint2* __restrict__ lo, int n4) {
    int i = blockIdx.x * blockDim.x + threadIdx.x;
    if (i >= n4) return;
    float4 v = in[i];
    __nv_bfloat16 h0 = __float2bfloat16(v.x), h1 = __float2bfloat16(v.y);
    __nv_bfloat16 h2 = __float2bfloat16(v.z), h3 = __float2bfloat16(v.w);
    __nv_bfloat16 l0 = __float2bfloat16(v.x - __bfloat162float(h0));
    __nv_bfloat16 l1 = __float2bfloat16(v.y - __bfloat162float(h1));
    __nv_bfloat16 l2 = __float2bfloat16(v.z - __bfloat162float(h2));
    __nv_bfloat16 l3 = __float2bfloat16(v.w - __bfloat162float(h3));
    uint2 uh, ul;
    uh.x = (uint32_t)__bfloat16_as_ushort(h0) | ((uint32_t)__bfloat16_as_ushort(h1) << 16);
    uh.y = (uint32_t)__bfloat16_as_ushort(h2) | ((uint32_t)__bfloat16_as_ushort(h3) << 16);
    ul.x = (uint32_t)__bfloat16_as_ushort(l0) | ((uint32_t)__bfloat16_as_ushort(l1) << 16);
    ul.y = (uint32_t)__bfloat16_as_ushort(l2) | ((uint32_t)__bfloat16_as_ushort(l3) << 16);
    hi[i] = uh;
    lo[i] = ul;
}

// Transpose + split: in[R,C] fp32 row-major -> hi/lo[C,R] bf16 row-major
__global__ void tsplit_kernel(const float* __restrict__ in,
                              __nv_bfloat16* __restrict__ hi,
                              __nv_bfloat16* __restrict__ lo, int R, int C) {
    __shared__ float t[32][33];
    int bx = blockIdx.x * 32;  // col base
    int by = blockIdx.y * 32;  // row base
    int tx = threadIdx.x, ty = threadIdx.y;
#pragma unroll
    for (int j = 0; j < 32; j += 8)
        t[ty + j][tx] = in[(size_t)(by + ty + j) * C + bx + tx];
    __syncthreads();
#pragma unroll
    for (int j = 0; j < 32; j += 8) {
        float v = t[tx][ty + j];
        __nv_bfloat16 h = __float2bfloat16(v);
        __nv_bfloat16 l = __float2bfloat16(v - __bfloat162float(h));
        size_t o = (size_t)(bx + ty + j) * R + by + tx;
        hi[o] = h;
        lo[o] = l;
    }
}

// Sum two split-K partials, emit fp32 sum (original layout) + transposed hi/lo
__global__ void tsplit2_kernel(const float* __restrict__ in0,
                               const float* __restrict__ in1,
                               __nv_bfloat16* __restrict__ hi,
                               __nv_bfloat16* __restrict__ lo,
                               float* __restrict__ sum, int R, int C) {
    __shared__ float t[32][33];
    int bx = blockIdx.x * 32;  // col base
    int by = blockIdx.y * 32;  // row base
    int tx = threadIdx.x, ty = threadIdx.y;
#pragma unroll
    for (int j = 0; j < 32; j += 8) {
        size_t idx = (size_t)(by + ty + j) * C + bx + tx;
        float v = in0[idx] + in1[idx];
        t[ty + j][tx] = v;
        sum[idx] = v;
    }
    __syncthreads();
#pragma unroll
    for (int j = 0; j < 32; j += 8) {
        float v = t[tx][ty + j];
        __nv_bfloat16 h = __float2bfloat16(v);
        __nv_bfloat16 l = __float2bfloat16(v - __bfloat162float(h));
        size_t o = (size_t)(bx + ty + j) * R + by + tx;
        hi[o] = h;
        lo[o] = l;
    }
}

// ---------------------------------------------------------------------------
// Split-GEMM on mma.sync (HMMA): C[M,BN] = A[M,K] @ B[BN,K]^T
//   D = Ah*Bh + Ah*Bl + Al*Bh (fp32 accum). BM=64, BK=64, 8 warps, 2-stage.
//   KS-way split-K over blockIdx.y; slice k writes C + k*M*BN.
// ---------------------------------------------------------------------------
template <int BN, int KS>
__global__ void __launch_bounds__(256)
gemm_mma_kernel(const __nv_bfloat16* __restrict__ Ah, const __nv_bfloat16* __restrict__ Al,
                const __nv_bfloat16* __restrict__ Bh, const __nv_bfloat16* __restrict__ Bl,
                float* __restrict__ C, int K) {
    constexpr int BM = 64, BK = 64;
    constexpr uint32_t ATILE = BM * BK * 2;           // 8192 B
    constexpr uint32_t BTILE = BN * BK * 2;           // 16384 / 8192 B
    constexpr uint32_t STAGE = 2 * ATILE + 2 * BTILE; // one stage: Ah,Al,Bh,Bl

    extern __shared__ __align__(1024) char smem[];
    const uint32_t sb = smem_u32(smem);

    const int tid = threadIdx.x;
    const int lane = tid & 31, wid = tid >> 5;
    const int warp_m = wid & 1;        // 2 m-blocks of 32
    const int warp_n = wid >> 1;       // 4 n-blocks of WTN
    constexpr int WTN = BN / 4;        // 32 or 16
    constexpr int NTILES = WTN / 8;    // 4 or 2 (n8 mma tiles per warp)
    constexpr int NPAIR = NTILES / 2;  // x4-ldmatrix pairs
    const int row0 = blockIdx.x * BM;

    const int Kper = K / KS;
    const int kbase = blockIdx.y * Kper;
    C += (size_t)blockIdx.y * ((size_t)gridDim.x * BM) * BN;

    float acc[2][NTILES][4];
#pragma unroll
    for (int i = 0; i < 2; i++)
#pragma unroll
        for (int j = 0; j < NTILES; j++)
#pragma unroll
            for (int k = 0; k < 4; k++) acc[i][j][k] = 0.0f;

    const int nst = Kper >> 6;

    auto load_stage = [&](int s) {
        const uint32_t base = sb + (uint32_t)(s & 1) * STAGE;
        const int k0 = kbase + s * BK;
#pragma unroll
        for (int i = 0; i < 2; i++) {
            int id = tid + i * 256;
            int r = id >> 3, kg = id & 7;
            uint32_t so = SW128((uint32_t)(r * 128 + kg * 16));
            size_t go = (size_t)(row0 + r) * K + k0 + kg * 8;
            cp16(base + so, Ah + go);
            cp16(base + ATILE + so, Al + go);
        }
#pragma unroll
        for (int i = 0; i < (BN * 8) / 256; i++) {
            int id = tid + i * 256;
            int r = id >> 3, kg = id & 7;
            uint32_t so = SW128((uint32_t)(r * 128 + kg * 16));
            size_t go = (size_t)r * K + k0 + kg * 8;
            cp16(base + 2 * ATILE + so, Bh + go);
            cp16(base + 2 * ATILE + BTILE + so, Bl + go);
        }
    };

    const int a_row = warp_m * 32 + (lane & 15);
    const int a_colb = (lane >> 4) << 4;
    const int b_row = warp_n * WTN + (lane & 7) + ((lane >> 4) << 3);
    const int b_colb = ((lane >> 3) & 1) << 4;

    load_stage(0);
    CP_COMMIT();

    for (int s = 0; s < nst; s++) {
        if (s + 1 < nst) {
            load_stage(s + 1);
            CP_COMMIT();
            CP_WAIT1();
        } else {
            CP_WAIT0();
        }
        __syncthreads();

        const uint32_t base = sb + (uint32_t)(s & 1) * STAGE;
#pragma unroll
        for (int ks = 0; ks < 4; ks++) {
            uint32_t ah[2][4], al[2][4];
#pragma unroll
            for (int mt = 0; mt < 2; mt++) {
                uint32_t off =
                    SW128((uint32_t)((a_row + mt * 16) * 128 + ks * 32 + a_colb));
                LDSM_X4(ah[mt], base + off);
                LDSM_X4(al[mt], base + ATILE + off);
            }
            uint32_t bh[NTILES][2], bl[NTILES][2];
#pragma unroll
            for (int p = 0; p < NPAIR; p++) {
                uint32_t off =
                    SW128((uint32_t)((b_row + p * 16) * 128 + ks * 32 + b_colb));
                uint32_t th[4], tl[4];
                LDSM_X4(th, base + 2 * ATILE + off);
                LDSM_X4(tl, base + 2 * ATILE + BTILE + off);
                bh[2 * p][0] = th[0]; bh[2 * p][1] = th[1];
                bh[2 * p + 1][0] = th[2]; bh[2 * p + 1][1] = th[3];
                bl[2 * p][0] = tl[0]; bl[2 * p][1] = tl[1];
                bl[2 * p + 1][0] = tl[2]; bl[2 * p + 1][1] = tl[3];
            }
#pragma unroll
            for (int mt = 0; mt < 2; mt++)
#pragma unroll
                for (int nt = 0; nt < NTILES; nt++) {
                    MMA16816(acc[mt][nt], ah[mt], bh[nt]);
                    MMA16816(acc[mt][nt], ah[mt], bl[nt]);
                    MMA16816(acc[mt][nt], al[mt], bh[nt]);
                }
        }
        __syncthreads();
    }

    const int m_base = row0 + warp_m * 32;
    const int n_base = warp_n * WTN;
#pragma unroll
    for (int mt = 0; mt < 2; mt++) {
#pragma unroll
        for (int nt = 0; nt < NTILES; nt++) {
            int r = m_base + mt * 16 + (lane >> 2);
            int c = n_base + nt * 8 + (lane & 3) * 2;
            *reinterpret_cast<float2*>(&C[(size_t)r * BN + c]) =
                make_float2(acc[mt][nt][0], acc[mt][nt][1]);
            *reinterpret_cast<float2*>(&C[(size_t)(r + 8) * BN + c]) =
                make_float2(acc[mt][nt][2], acc[mt][nt][3]);
        }
    }
}

// ---------------------------------------------------------------------------
// Combine: out = act(h0*Y0 + h1*Y1 + h2*(Y2a+Y2b) + b[col]), vectorized
// ---------------------------------------------------------------------------
__global__ void combine_kernel(int total4, int N,
                               const float4* __restrict__ Y0,
                               const float4* __restrict__ Y1,
                               const float4* __restrict__ Y2a,
                               const float4* __restrict__ Y2b,
                               const float* __restrict__ h,
                               const float* __restrict__ b,
                               float4* __restrict__ out, int do_relu) {
    int i = blockIdx.x * blockDim.x + threadIdx.x;
    if (i >= total4) return;
    int j = (i * 4) & (N - 1);
    float h0 = h[0], h1 = h[1], h2 = h[2];
    float4 a = Y0[i], c = Y1[i], da = Y2a[i], db = Y2b[i];
    float4 r;
    r.x = fmaf(h0, a.x, fmaf(h1, c.x, fmaf(h2, da.x + db.x, b[j])));
    r.y = fmaf(h0, a.y, fmaf(h1, c.y, fmaf(h2, da.y + db.y, b[j + 1])));
    r.z = fmaf(h0, a.z, fmaf(h1, c.z, fmaf(h2, da.z + db.z, b[j + 2])));
    r.w = fmaf(h0, a.w, fmaf(h1, c.w, fmaf(h2, da.w + db.w, b[j + 3])));
    if (do_relu) {
        r.x = fmaxf(r.x, 0.f); r.y = fmaxf(r.y, 0.f);
        r.z = fmaxf(r.z, 0.f); r.w = fmaxf(r.w, 0.f);
    }
    out[i] = r;
}

// ---------------------------------------------------------------------------
// Host orchestration
// ---------------------------------------------------------------------------
static void run_split(const float* x, __nv_bfloat16* hi, __nv_bfloat16* lo, size_t n) {
    int n4 = (int)(n / 4);
    split_kernel<<<(n4 + 255) / 256, 256>>>((const float4*)x, (uint2*)hi, (uint2*)lo, n4);
}

static void run_tsplit(const float* in, __nv_bfloat16* hi, __nv_bfloat16* lo, int R, int C) {
    dim3 grid(C / 32, R / 32), block(32, 8);
    tsplit_kernel<<<grid, block>>>(in, hi, lo, R, C);
}

static void run_tsplit2(const float* in0, const float* in1, __nv_bfloat16* hi,
                        __nv_bfloat16* lo, float* sum, int R, int C) {
    dim3 grid(C / 32, R / 32), block(32, 8);
    tsplit2_kernel<<<grid, block>>>(in0, in1, hi, lo, sum, R, C);
}

template <int BN, int KS>
static void run_gemm(const __nv_bfloat16* Ah, const __nv_bfloat16* Al,
                     const __nv_bfloat16* Bh, const __nv_bfloat16* Bl,
                     float* C, int K) {
    constexpr uint32_t STAGE = 2 * (64 * 64 * 2) + 2 * (BN * 64 * 2);
    constexpr uint32_t smem_bytes = 2 * STAGE;
    cudaFuncSetAttribute(gemm_mma_kernel<BN, KS>,
                         cudaFuncAttributeMaxDynamicSharedMemorySize, smem_bytes);
    dim3 grid(NODES / 64, KS);
    gemm_mma_kernel<BN, KS><<<grid, 256, smem_bytes>>>(Ah, Al, Bh, Bl, C, K);
}

static void run_combine(const float* Y0, const float* Y1, const float* Y2a,
                        const float* Y2b, const float* h, const float* b,
                        float* out, int N, int relu) {
    int total4 = NODES * N / 4;
    combine_kernel<<<(total4 + 255) / 256, 256>>>(
        total4, N, (const float4*)Y0, (const float4*)Y1, (const float4*)Y2a,
        (const float4*)Y2b, h, b, (float4*)out, relu);
}

extern "C" void kernel_launch(void* const* d_in, const int* in_sizes, int n_in,
                              void* d_out, int out_size) {
    const float* S  = (const float*)d_in[0];
    const float* X  = (const float*)d_in[1];
    const float* W1 = (const float*)d_in[2];
    const float* h1 = (const float*)d_in[3];
    const float* b1 = (const float*)d_in[4];
    const float* W2 = (const float*)d_in[5];
    const float* h2 = (const float*)d_in[6];
    const float* b2 = (const float*)d_in[7];
    const float* W3 = (const float*)d_in[8];
    const float* h3 = (const float*)d_in[9];
    const float* b3 = (const float*)d_in[10];
    float* out = (float*)d_out;

    __nv_bfloat16 *Sh, *Sl, *Ah, *Al, *Bh, *Bl;
    float *Y0, *Y1, *P, *X1, *X2;
    cudaGetSymbolAddress((void**)&Sh, g_Sh);
    cudaGetSymbolAddress((void**)&Sl, g_Sl);
    cudaGetSymbolAddress((void**)&Ah, g_Ah);
    cudaGetSymbolAddress((void**)&Al, g_Al);
    cudaGetSymbolAddress((void**)&Bh, g_Bh);
    cudaGetSymbolAddress((void**)&Bl, g_Bl);
    cudaGetSymbolAddress((void**)&Y0, g_Y0);
    cudaGetSymbolAddress((void**)&Y1, g_Y1);
    cudaGetSymbolAddress((void**)&P, g_P);
    cudaGetSymbolAddress((void**)&X1, g_X1);
    cudaGetSymbolAddress((void**)&X2, g_X2);

    float* P1_128 = P + (size_t)NODES * HID;      // slice-1 base for BN=128
    float* P1_64  = P + (size_t)NODES * OUT_DIM;  // slice-1 base for BN=64

    // S -> bf16 hi/lo (recomputed every launch; caching would break determinism)
    run_split(S, Sh, Sl, (size_t)NODES * NODES);

    // -------- layer 1 (N=128, ReLU) --------
    run_split(X, Ah, Al, (size_t)NODES * IN_DIM);
    run_tsplit(W1, Bh, Bl, IN_DIM, HID);
    run_gemm<HID, 1>(Ah, Al, Bh, Bl, Y0, IN_DIM);   // Y0 = X@W1
    run_tsplit(Y0, Bh, Bl, NODES, HID);
    run_gemm<HID, 2>(Sh, Sl, Bh, Bl, P, NODES);     // P|P1 = S@Y0 partials
    run_tsplit2(P, P1_128, Bh, Bl, Y1, NODES, HID); // Y1 = sum; split Y1^T
    run_gemm<HID, 2>(Sh, Sl, Bh, Bl, P, NODES);     // P|P1 = S@Y1 partials
    run_combine(Y0, Y1, P, P1_128, h1, b1, X1, HID, 1);

    // -------- layer 2 (N=128, ReLU) --------
    run_split(X1, Ah, Al, (size_t)NODES * HID);
    run_tsplit(W2, Bh, Bl, HID, HID);
    run_gemm<HID, 1>(Ah, Al, Bh, Bl, Y0, HID);
    run_tsplit(Y0, Bh, Bl, NODES, HID);
    run_gemm<HID, 2>(Sh, Sl, Bh, Bl, P, NODES);
    run_tsplit2(P, P1_128, Bh, Bl, Y1, NODES, HID);
    run_gemm<HID, 2>(Sh, Sl, Bh, Bl, P, NODES);
    run_combine(Y0, Y1, P, P1_128, h2, b2, X2, HID, 1);

    // -------- layer 3 (N=64, identity) --------
    run_split(X2, Ah, Al, (size_t)NODES * HID);
    run_tsplit(W3, Bh, Bl, HID, OUT_DIM);
    run_gemm<OUT_DIM, 1>(Ah, Al, Bh, Bl, Y0, HID);
    run_tsplit(Y0, Bh, Bl, NODES, OUT_DIM);
    run_gemm<OUT_DIM, 2>(Sh, Sl, Bh, Bl, P, NODES);
    run_tsplit2(P, P1_64, Bh, Bl, Y1, NODES, OUT_DIM);
    run_gemm<OUT_DIM, 2>(Sh, Sl, Bh, Bl, P, NODES);
    run_combine(Y0, Y1, P, P1_64, h3, b3, out, OUT_DIM, 0);
}